// round 3
// baseline (speedup 1.0000x reference)
#include <cuda_runtime.h>

#define D_DIM   768
#define F4_ROW  (D_DIM / 4)        // 192 float4 per row
#define F4_LANE 6                  // float4 per lane (192/32)
#define WARPS   4
#define NTHR    (WARPS * 32)       // 128 threads
#define RPW     8                  // rows per warp
#define LN_EPS  1e-6f

__global__ __launch_bounds__(NTHR, 6)
void hier_attn_ln_kernel(const int*   __restrict__ ids,
                         const float* __restrict__ pooler,
                         const float* __restrict__ emb,     // (V,2)
                         const float* __restrict__ Wd,      // (2,D)
                         const float* __restrict__ bd,      // (D)
                         const float* __restrict__ gamma,   // (D)
                         const float* __restrict__ beta,    // (D)
                         float*       __restrict__ out,
                         int L)
{
    __shared__ float4 sg[F4_ROW];   // gamma
    __shared__ float4 sb[F4_ROW];   // beta

    const int b    = blockIdx.y;
    const int warp = threadIdx.x >> 5;
    const int lane = threadIdx.x & 31;
    const int t    = threadIdx.x;

    // ---- stage gamma/beta into smem once per block ----
    {
        const float4* GG = reinterpret_cast<const float4*>(gamma);
        const float4* BE = reinterpret_cast<const float4*>(beta);
        #pragma unroll
        for (int i = t; i < F4_ROW; i += NTHR) {
            sg[i] = GG[i];
            sb[i] = BE[i];
        }
    }

    // ---- per-batch x vector (registers), Sx / xx reduced once ----
    const int   id = __ldg(ids + b);
    const float e0 = __ldg(emb + 2 * id);
    const float e1 = __ldg(emb + 2 * id + 1);

    const float4* W0 = reinterpret_cast<const float4*>(Wd);
    const float4* W1 = reinterpret_cast<const float4*>(Wd + D_DIM);
    const float4* BB = reinterpret_cast<const float4*>(bd);

    float4 x[F4_LANE];
    float Sx = 0.f, xx = 0.f;
    #pragma unroll
    for (int j = 0; j < F4_LANE; ++j) {
        const int c = lane + 32 * j;
        float4 w0 = W0[c], w1 = W1[c], bb = BB[c];
        float4 xv;
        xv.x = fmaf(e0, w0.x, fmaf(e1, w1.x, bb.x));
        xv.y = fmaf(e0, w0.y, fmaf(e1, w1.y, bb.y));
        xv.z = fmaf(e0, w0.z, fmaf(e1, w1.z, bb.z));
        xv.w = fmaf(e0, w0.w, fmaf(e1, w1.w, bb.w));
        x[j] = xv;
        Sx += xv.x + xv.y + xv.z + xv.w;
        xx = fmaf(xv.x, xv.x, fmaf(xv.y, xv.y, fmaf(xv.z, xv.z, fmaf(xv.w, xv.w, xx))));
    }
    #pragma unroll
    for (int off = 16; off > 0; off >>= 1) {
        Sx += __shfl_xor_sync(0xffffffffu, Sx, off);
        xx += __shfl_xor_sync(0xffffffffu, xx, off);
    }

    __syncthreads();   // gamma/beta staged

    const int l0 = (blockIdx.x * WARPS + warp) * RPW;
    if (l0 >= L) return;

    const float invD = 1.0f / (float)D_DIM;
    const size_t rowBase = ((size_t)b * L + l0) * D_DIM;

    #pragma unroll 2
    for (int r = 0; r < RPW; ++r) {
        if (l0 + r >= L) break;
        const float4* prow = reinterpret_cast<const float4*>(pooler + rowBase + (size_t)r * D_DIM);
        float4*       orow = reinterpret_cast<float4*>(out + rowBase + (size_t)r * D_DIM);

        float4 p[F4_LANE];
        #pragma unroll
        for (int j = 0; j < F4_LANE; ++j)
            p[j] = prow[lane + 32 * j];

        float pp = 0.f, px = 0.f, Sp = 0.f;
        #pragma unroll
        for (int j = 0; j < F4_LANE; ++j) {
            pp = fmaf(p[j].x, p[j].x, fmaf(p[j].y, p[j].y, fmaf(p[j].z, p[j].z, fmaf(p[j].w, p[j].w, pp))));
            px = fmaf(p[j].x, x[j].x, fmaf(p[j].y, x[j].y, fmaf(p[j].z, x[j].z, fmaf(p[j].w, x[j].w, px))));
            Sp += p[j].x + p[j].y + p[j].z + p[j].w;
        }
        #pragma unroll
        for (int off = 16; off > 0; off >>= 1) {
            pp += __shfl_xor_sync(0xffffffffu, pp, off);
            px += __shfl_xor_sync(0xffffffffu, px, off);
            Sp += __shfl_xor_sync(0xffffffffu, Sp, off);
        }

        // 2x2 safe softmax; rows [pp,px] and [px,xx]
        float m0  = fmaxf(pp, px);
        float e00 = __expf(pp - m0), e01 = __expf(px - m0);
        float a00 = e00 / (e00 + e01), a01 = 1.0f - a00;
        float m1  = fmaxf(px, xx);
        float e10 = __expf(px - m1), e11 = __expf(xx - m1);
        float a10 = e10 / (e10 + e11), a11 = 1.0f - a10;

        float wp = a00 + a10;
        float wx = a01 + a11;

        // analytic layernorm stats of summed = wp*p + wx*x
        float mean = (wp * Sp + wx * Sx) * invD;
        float ss2  = wp*wp*pp + 2.0f*wp*wx*px + wx*wx*xx;
        float var  = ss2 * invD - mean * mean;
        float inv  = rsqrtf(var + LN_EPS);
        float cwp  = wp * inv;
        float cwx  = wx * inv;
        float cm   = mean * inv;

        #pragma unroll
        for (int j = 0; j < F4_LANE; ++j) {
            const int c = lane + 32 * j;
            float4 g  = sg[c];
            float4 be = sb[c];
            float4 o;
            o.x = fmaf(fmaf(cwp, p[j].x, fmaf(cwx, x[j].x, -cm)), g.x, be.x);
            o.y = fmaf(fmaf(cwp, p[j].y, fmaf(cwx, x[j].y, -cm)), g.y, be.y);
            o.z = fmaf(fmaf(cwp, p[j].z, fmaf(cwx, x[j].z, -cm)), g.z, be.z);
            o.w = fmaf(fmaf(cwp, p[j].w, fmaf(cwx, x[j].w, -cm)), g.w, be.w);
            orow[c] = o;
        }
    }
}

extern "C" void kernel_launch(void* const* d_in, const int* in_sizes, int n_in,
                              void* d_out, int out_size)
{
    const int*   ids    = (const int*)  d_in[0];
    const float* pooler = (const float*)d_in[1];
    const float* emb    = (const float*)d_in[2];
    const float* Wd     = (const float*)d_in[3];
    const float* bd     = (const float*)d_in[4];
    const float* gamma  = (const float*)d_in[5];
    const float* beta   = (const float*)d_in[6];
    float* out = (float*)d_out;

    const int B = in_sizes[0];                      // ids is (B,1)
    const int L = in_sizes[1] / (B * D_DIM);        // pooler is (B,L,D)

    dim3 grid((L + WARPS * RPW - 1) / (WARPS * RPW), B);
    hier_attn_ln_kernel<<<grid, NTHR>>>(ids, pooler, emb, Wd, bd, gamma, beta, out, L);
}

// round 4
// speedup vs baseline: 1.5697x; 1.5697x over previous
#include <cuda_runtime.h>

#define D_DIM   768
#define F4_ROW  (D_DIM / 4)        // 192 float4 per row
#define F4_LANE 6                  // float4 per lane (192/32)
#define WARPS   8
#define NTHR    (WARPS * 32)       // 256 threads
#define RPW     8                  // rows per warp
#define LN_EPS  1e-6f

__global__ __launch_bounds__(NTHR)
void hier_attn_ln_kernel(const int*   __restrict__ ids,
                         const float* __restrict__ pooler,
                         const float* __restrict__ emb,     // (V,2)
                         const float* __restrict__ Wd,      // (2,D)
                         const float* __restrict__ bd,      // (D)
                         const float* __restrict__ gamma,   // (D)
                         const float* __restrict__ beta,    // (D)
                         float*       __restrict__ out,
                         int L)
{
    __shared__ float4 sg[F4_ROW];   // gamma
    __shared__ float4 sb[F4_ROW];   // beta

    const int b    = blockIdx.y;
    const int warp = threadIdx.x >> 5;
    const int lane = threadIdx.x & 31;
    const int t    = threadIdx.x;

    // ---- stage gamma/beta into smem once per block ----
    {
        const float4* GG = reinterpret_cast<const float4*>(gamma);
        const float4* BE = reinterpret_cast<const float4*>(beta);
        if (t < F4_ROW) {
            sg[t] = GG[t];
            sb[t] = BE[t];
        }
    }

    // ---- per-batch x vector (registers), Sx / xx reduced once ----
    const int   id = __ldg(ids + b);
    const float e0 = __ldg(emb + 2 * id);
    const float e1 = __ldg(emb + 2 * id + 1);

    const float4* W0 = reinterpret_cast<const float4*>(Wd);
    const float4* W1 = reinterpret_cast<const float4*>(Wd + D_DIM);
    const float4* BB = reinterpret_cast<const float4*>(bd);

    float4 x[F4_LANE];
    float Sx = 0.f, xx = 0.f;
    #pragma unroll
    for (int j = 0; j < F4_LANE; ++j) {
        const int c = lane + 32 * j;
        float4 w0 = W0[c], w1 = W1[c], bb = BB[c];
        float4 xv;
        xv.x = fmaf(e0, w0.x, fmaf(e1, w1.x, bb.x));
        xv.y = fmaf(e0, w0.y, fmaf(e1, w1.y, bb.y));
        xv.z = fmaf(e0, w0.z, fmaf(e1, w1.z, bb.z));
        xv.w = fmaf(e0, w0.w, fmaf(e1, w1.w, bb.w));
        x[j] = xv;
        Sx += xv.x + xv.y + xv.z + xv.w;
        xx = fmaf(xv.x, xv.x, fmaf(xv.y, xv.y, fmaf(xv.z, xv.z, fmaf(xv.w, xv.w, xx))));
    }
    #pragma unroll
    for (int off = 16; off > 0; off >>= 1) {
        Sx += __shfl_xor_sync(0xffffffffu, Sx, off);
        xx += __shfl_xor_sync(0xffffffffu, xx, off);
    }

    __syncthreads();   // gamma/beta staged

    const int l0 = (blockIdx.x * WARPS + warp) * RPW;
    if (l0 >= L) return;
    const int nrows = min(RPW, L - l0);

    const float invD = 1.0f / (float)D_DIM;
    const float* rowPtr = pooler + ((size_t)b * L + l0) * D_DIM;
    float*       outPtr = out    + ((size_t)b * L + l0) * D_DIM;

    // ---- explicit double-buffered row pipeline ----
    float4 pbuf[2][F4_LANE];

    // prologue: load row 0 (streaming loads — no reuse, bypass L2 persist)
    #pragma unroll
    for (int j = 0; j < F4_LANE; ++j)
        pbuf[0][j] = __ldcs(reinterpret_cast<const float4*>(rowPtr) + lane + 32 * j);

    #pragma unroll
    for (int r = 0; r < RPW; ++r) {
        if (r >= nrows) break;
        float4 (&p)[F4_LANE]  = pbuf[r & 1];
        float4 (&pn)[F4_LANE] = pbuf[(r + 1) & 1];

        // prefetch next row BEFORE the serial chain
        if (r + 1 < nrows) {
            const float4* nrow = reinterpret_cast<const float4*>(rowPtr + (size_t)(r + 1) * D_DIM);
            #pragma unroll
            for (int j = 0; j < F4_LANE; ++j)
                pn[j] = __ldcs(nrow + lane + 32 * j);
        }

        float pp = 0.f, px = 0.f, Sp = 0.f;
        #pragma unroll
        for (int j = 0; j < F4_LANE; ++j) {
            pp = fmaf(p[j].x, p[j].x, fmaf(p[j].y, p[j].y, fmaf(p[j].z, p[j].z, fmaf(p[j].w, p[j].w, pp))));
            px = fmaf(p[j].x, x[j].x, fmaf(p[j].y, x[j].y, fmaf(p[j].z, x[j].z, fmaf(p[j].w, x[j].w, px))));
            Sp += p[j].x + p[j].y + p[j].z + p[j].w;
        }
        #pragma unroll
        for (int off = 16; off > 0; off >>= 1) {
            pp += __shfl_xor_sync(0xffffffffu, pp, off);
            px += __shfl_xor_sync(0xffffffffu, px, off);
            Sp += __shfl_xor_sync(0xffffffffu, Sp, off);
        }

        // 2x2 safe softmax; rows [pp,px] and [px,xx]
        float m0  = fmaxf(pp, px);
        float e00 = __expf(pp - m0), e01 = __expf(px - m0);
        float a00 = e00 / (e00 + e01), a01 = 1.0f - a00;
        float m1  = fmaxf(px, xx);
        float e10 = __expf(px - m1), e11 = __expf(xx - m1);
        float a10 = e10 / (e10 + e11), a11 = 1.0f - a10;

        float wp = a00 + a10;
        float wx = a01 + a11;

        // analytic layernorm stats of summed = wp*p + wx*x
        float mean = (wp * Sp + wx * Sx) * invD;
        float ss2  = wp*wp*pp + 2.0f*wp*wx*px + wx*wx*xx;
        float var  = ss2 * invD - mean * mean;
        float inv  = rsqrtf(var + LN_EPS);
        float cwp  = wp * inv;
        float cwx  = wx * inv;
        float cm   = mean * inv;

        float4* orow = reinterpret_cast<float4*>(outPtr + (size_t)r * D_DIM);
        #pragma unroll
        for (int j = 0; j < F4_LANE; ++j) {
            const int c = lane + 32 * j;
            float4 g  = sg[c];
            float4 be = sb[c];
            float4 o;
            o.x = fmaf(fmaf(cwp, p[j].x, fmaf(cwx, x[j].x, -cm)), g.x, be.x);
            o.y = fmaf(fmaf(cwp, p[j].y, fmaf(cwx, x[j].y, -cm)), g.y, be.y);
            o.z = fmaf(fmaf(cwp, p[j].z, fmaf(cwx, x[j].z, -cm)), g.z, be.z);
            o.w = fmaf(fmaf(cwp, p[j].w, fmaf(cwx, x[j].w, -cm)), g.w, be.w);
            __stcs(orow + c, o);
        }
    }
}

extern "C" void kernel_launch(void* const* d_in, const int* in_sizes, int n_in,
                              void* d_out, int out_size)
{
    const int*   ids    = (const int*)  d_in[0];
    const float* pooler = (const float*)d_in[1];
    const float* emb    = (const float*)d_in[2];
    const float* Wd     = (const float*)d_in[3];
    const float* bd     = (const float*)d_in[4];
    const float* gamma  = (const float*)d_in[5];
    const float* beta   = (const float*)d_in[6];
    float* out = (float*)d_out;

    const int B = in_sizes[0];                      // ids is (B,1)
    const int L = in_sizes[1] / (B * D_DIM);        // pooler is (B,L,D)

    dim3 grid((L + WARPS * RPW - 1) / (WARPS * RPW), B);
    hier_attn_ln_kernel<<<grid, NTHR>>>(ids, pooler, emb, Wd, bd, gamma, beta, out, L);
}

// round 6
// speedup vs baseline: 1.5724x; 1.0017x over previous
#include <cuda_runtime.h>

#define D_DIM   768
#define F4_ROW  (D_DIM / 4)        // 192 float4 per row
#define F4_LANE 6                  // float4 per lane (192/32)
#define WARPS   8
#define NTHR    (WARPS * 32)       // 256 threads
#define RPW     4                  // rows per warp
#define LN_EPS  1e-6f

__global__ __launch_bounds__(NTHR, 3)
void hier_attn_ln_kernel(const int*   __restrict__ ids,
                         const float* __restrict__ pooler,
                         const float* __restrict__ emb,     // (V,2)
                         const float* __restrict__ Wd,      // (2,D)
                         const float* __restrict__ bd,      // (D)
                         const float* __restrict__ gamma,   // (D)
                         const float* __restrict__ beta,    // (D)
                         float*       __restrict__ out,
                         int L)
{
    __shared__ float4 sX [F4_ROW];   // x
    __shared__ float4 sG [F4_ROW];   // gamma
    __shared__ float4 sGX[F4_ROW];   // gamma * x
    __shared__ float4 sBE[F4_ROW];   // beta
    __shared__ float  sred[WARPS][2];

    const int b    = blockIdx.y;
    const int warp = threadIdx.x >> 5;
    const int lane = threadIdx.x & 31;
    const int t    = threadIdx.x;

    // ---- per-block setup: build x, gamma, gamma*x, beta in smem; reduce Sx, xx ----
    const int   id = __ldg(ids + b);
    const float e0 = __ldg(emb + 2 * id);
    const float e1 = __ldg(emb + 2 * id + 1);

    float sxp = 0.f, xxp = 0.f;
    if (t < F4_ROW) {
        float4 w0 = reinterpret_cast<const float4*>(Wd)[t];
        float4 w1 = reinterpret_cast<const float4*>(Wd + D_DIM)[t];
        float4 bb = reinterpret_cast<const float4*>(bd)[t];
        float4 xv;
        xv.x = fmaf(e0, w0.x, fmaf(e1, w1.x, bb.x));
        xv.y = fmaf(e0, w0.y, fmaf(e1, w1.y, bb.y));
        xv.z = fmaf(e0, w0.z, fmaf(e1, w1.z, bb.z));
        xv.w = fmaf(e0, w0.w, fmaf(e1, w1.w, bb.w));
        float4 g  = reinterpret_cast<const float4*>(gamma)[t];
        float4 be = reinterpret_cast<const float4*>(beta)[t];
        float4 gx = make_float4(g.x * xv.x, g.y * xv.y, g.z * xv.z, g.w * xv.w);
        sX [t] = xv;
        sG [t] = g;
        sGX[t] = gx;
        sBE[t] = be;
        sxp = xv.x + xv.y + xv.z + xv.w;
        xxp = fmaf(xv.x, xv.x, fmaf(xv.y, xv.y, fmaf(xv.z, xv.z, xv.w * xv.w)));
    }
    #pragma unroll
    for (int off = 16; off > 0; off >>= 1) {
        sxp += __shfl_xor_sync(0xffffffffu, sxp, off);
        xxp += __shfl_xor_sync(0xffffffffu, xxp, off);
    }
    if (lane == 0) { sred[warp][0] = sxp; sred[warp][1] = xxp; }
    __syncthreads();
    float Sx = 0.f, xx = 0.f;
    #pragma unroll
    for (int w = 0; w < WARPS; ++w) { Sx += sred[w][0]; xx += sred[w][1]; }

    const int l0 = (blockIdx.x * WARPS + warp) * RPW;
    if (l0 >= L) return;
    const int nrows = min(RPW, L - l0);

    const float invD = 1.0f / (float)D_DIM;
    const float* rowPtr = pooler + ((size_t)b * L + l0) * D_DIM;
    float*       outPtr = out    + ((size_t)b * L + l0) * D_DIM;

    // ---- explicit double-buffered row pipeline ----
    float4 pbuf[2][F4_LANE];
    #pragma unroll
    for (int j = 0; j < F4_LANE; ++j)
        pbuf[0][j] = __ldcs(reinterpret_cast<const float4*>(rowPtr) + lane + 32 * j);

    #pragma unroll
    for (int r = 0; r < RPW; ++r) {
        if (r >= nrows) break;
        float4 (&p)[F4_LANE]  = pbuf[r & 1];
        float4 (&pn)[F4_LANE] = pbuf[(r + 1) & 1];

        // prefetch next row before the dependent chain
        if (r + 1 < nrows) {
            const float4* nrow = reinterpret_cast<const float4*>(rowPtr + (size_t)(r + 1) * D_DIM);
            #pragma unroll
            for (int j = 0; j < F4_LANE; ++j)
                pn[j] = __ldcs(nrow + lane + 32 * j);
        }

        float pp = 0.f, px = 0.f, Sp = 0.f;
        #pragma unroll
        for (int j = 0; j < F4_LANE; ++j) {
            const float4 xv = sX[lane + 32 * j];
            pp = fmaf(p[j].x, p[j].x, fmaf(p[j].y, p[j].y, fmaf(p[j].z, p[j].z, fmaf(p[j].w, p[j].w, pp))));
            px = fmaf(p[j].x, xv.x,   fmaf(p[j].y, xv.y,   fmaf(p[j].z, xv.z,   fmaf(p[j].w, xv.w,   px))));
            Sp += p[j].x + p[j].y + p[j].z + p[j].w;
        }
        #pragma unroll
        for (int off = 16; off > 0; off >>= 1) {
            pp += __shfl_xor_sync(0xffffffffu, pp, off);
            px += __shfl_xor_sync(0xffffffffu, px, off);
            Sp += __shfl_xor_sync(0xffffffffu, Sp, off);
        }

        // 2x2 safe softmax; rows [pp,px] and [px,xx]
        float m0  = fmaxf(pp, px);
        float e00 = __expf(pp - m0), e01 = __expf(px - m0);
        float a00 = e00 / (e00 + e01), a01 = 1.0f - a00;
        float m1  = fmaxf(px, xx);
        float e10 = __expf(px - m1), e11 = __expf(xx - m1);
        float a10 = e10 / (e10 + e11), a11 = 1.0f - a10;

        float wp = a00 + a10;
        float wx = a01 + a11;

        // analytic layernorm stats of summed = wp*p + wx*x
        float mean = (wp * Sp + wx * Sx) * invD;
        float ss2  = wp*wp*pp + 2.0f*wp*wx*px + wx*wx*xx;
        float var  = ss2 * invD - mean * mean;
        float inv  = rsqrtf(var + LN_EPS);
        float cwp  = wp * inv;
        float cwx  = wx * inv;
        float ncm  = -mean * inv;

        // o = cwp*(p*g) + cwx*(g*x) + (-cm)*g + beta
        float4* orow = reinterpret_cast<float4*>(outPtr + (size_t)r * D_DIM);
        #pragma unroll
        for (int j = 0; j < F4_LANE; ++j) {
            const int c = lane + 32 * j;
            const float4 g  = sG[c];
            const float4 gx = sGX[c];
            const float4 be = sBE[c];
            float4 o;
            o.x = fmaf(cwp, p[j].x * g.x, fmaf(cwx, gx.x, fmaf(ncm, g.x, be.x)));
            o.y = fmaf(cwp, p[j].y * g.y, fmaf(cwx, gx.y, fmaf(ncm, g.y, be.y)));
            o.z = fmaf(cwp, p[j].z * g.z, fmaf(cwx, gx.z, fmaf(ncm, g.z, be.z)));
            o.w = fmaf(cwp, p[j].w * g.w, fmaf(cwx, gx.w, fmaf(ncm, g.w, be.w)));
            __stcs(orow + c, o);
        }
    }
}

extern "C" void kernel_launch(void* const* d_in, const int* in_sizes, int n_in,
                              void* d_out, int out_size)
{
    const int*   ids    = (const int*)  d_in[0];
    const float* pooler = (const float*)d_in[1];
    const float* emb    = (const float*)d_in[2];
    const float* Wd     = (const float*)d_in[3];
    const float* bd     = (const float*)d_in[4];
    const float* gamma  = (const float*)d_in[5];
    const float* beta   = (const float*)d_in[6];
    float* out = (float*)d_out;

    const int B = in_sizes[0];                      // ids is (B,1)
    const int L = in_sizes[1] / (B * D_DIM);        // pooler is (B,L,D)

    dim3 grid((L + WARPS * RPW - 1) / (WARPS * RPW), B);
    hier_attn_ln_kernel<<<grid, NTHR>>>(ids, pooler, emb, Wd, bd, gamma, beta, out, L);
}